// round 13
// baseline (speedup 1.0000x reference)
#include <cuda_runtime.h>
#include <cuda_bf16.h>
#include <stdint.h>

// Problem constants
#define T_SEQ 512
#define BATCH 64
#define DIM   1024
#define LAT   1024
#define NPACK 4096            // 4*LAT, gate-interleaved packed columns: p = 4*j + g
#define M1    32768           // T_SEQ*BATCH
#define NCTA  128             // persistent grid (1 CTA/SM by smem)

// ---------------------------------------------------------------------------
// Device scratch (static __device__ arrays; no allocations anywhere)
// ---------------------------------------------------------------------------
__device__ float          g_gx[134217728];          // [M1][NPACK] fp32 x-part gates
__device__ __nv_bfloat16  g_Wxh[4194304], g_Wxl[4194304];  // Wx packed [NPACK][DIM] hi/lo
__device__ __nv_bfloat16  g_Whh[4194304], g_Whl[4194304];  // Wh packed [NPACK][LAT] hi/lo
__device__ __nv_bfloat16  g_xh[33554432], g_xl[33554432];  // x split   [M1][DIM]    hi/lo
// h state, double buffered, SWIZZLED k-major layout:
//   idx(j, r) = (j>>3)*512 + (j&7)*64 + (r ^ ((j&7)<<3))   (bf16 units)
// => any k-range [64c, 64c+64) x all 64 rows is a contiguous 8 KB block,
//    SW128-pattern swizzled for conflict-free ldmatrix.
__device__ __nv_bfloat16  g_hsh[2][65536], g_hsl[2][65536];
__device__ float          g_c[65536];                       // c state fp32
__device__ float          g_bias[4096];                     // packed bias
__device__ unsigned       g_ctr[8];                         // spread arrival counters
__device__ unsigned       g_phase;                          // barrier phase broadcast

// ---------------------------------------------------------------------------
// mma.sync m16n8k16 bf16 helper (fp32 accumulate)
// ---------------------------------------------------------------------------
__device__ __forceinline__ void mma_bf16(float c[4], const uint32_t a[4], const uint32_t b[2]) {
    asm volatile(
        "mma.sync.aligned.m16n8k16.row.col.f32.bf16.bf16.f32 "
        "{%0,%1,%2,%3}, {%4,%5,%6,%7}, {%8,%9}, {%0,%1,%2,%3};\n"
        : "+f"(c[0]), "+f"(c[1]), "+f"(c[2]), "+f"(c[3])
        : "r"(a[0]), "r"(a[1]), "r"(a[2]), "r"(a[3]), "r"(b[0]), "r"(b[1]));
}

// cp.async helpers (16B, L2-only path: .cg) — used by gemm_x only
__device__ __forceinline__ void cp_async16(void* sptr, const void* gptr) {
    uint32_t s = (uint32_t)__cvta_generic_to_shared(sptr);
    asm volatile("cp.async.cg.shared.global [%0], [%1], 16;\n" :: "r"(s), "l"(gptr));
}
__device__ __forceinline__ void cp_commit() { asm volatile("cp.async.commit_group;\n"); }
__device__ __forceinline__ void cp_wait1()  { asm volatile("cp.async.wait_group 1;\n"); }
__device__ __forceinline__ void cp_wait0()  { asm volatile("cp.async.wait_group 0;\n"); }

// bulk copy + mbarrier helpers (recurrent kernel)
__device__ __forceinline__ void mbar_init(uint32_t mbar, uint32_t count) {
    asm volatile("mbarrier.init.shared.b64 [%0], %1;" :: "r"(mbar), "r"(count) : "memory");
}
__device__ __forceinline__ void mbar_expect_tx(uint32_t mbar, uint32_t bytes) {
    asm volatile("mbarrier.arrive.expect_tx.shared.b64 _, [%0], %1;"
                 :: "r"(mbar), "r"(bytes) : "memory");
}
__device__ __forceinline__ void mbar_wait(uint32_t mbar, uint32_t parity) {
    uint32_t done;
    asm volatile(
        "{\n\t.reg .pred p;\n\t"
        "mbarrier.try_wait.parity.acquire.cta.shared::cta.b64 p, [%1], %2;\n\t"
        "selp.b32 %0, 1, 0, p;\n\t}"
        : "=r"(done) : "r"(mbar), "r"(parity) : "memory");
    if (!done) {
        asm volatile(
            "{\n\t.reg .pred P1;\n\t"
            "WAIT_LOOP_%=:\n\t"
            "mbarrier.try_wait.parity.acquire.cta.shared::cta.b64 P1, [%0], %1, 0x989680;\n\t"
            "@P1 bra.uni WAIT_DONE_%=;\n\t"
            "bra.uni WAIT_LOOP_%=;\n\t"
            "WAIT_DONE_%=:\n\t}"
            :: "r"(mbar), "r"(parity) : "memory");
    }
}
__device__ __forceinline__ void bulk_g2s(uint32_t dst, const void* src, uint32_t bytes,
                                         uint32_t mbar) {
    asm volatile(
        "cp.async.bulk.shared::cta.global.mbarrier::complete_tx::bytes [%0], [%1], %2, [%3];"
        :: "r"(dst), "l"(src), "r"(bytes), "r"(mbar) : "memory");
}
__device__ __forceinline__ void ldmatrix_x4_trans(uint32_t* r, uint32_t addr) {
    asm volatile("ldmatrix.sync.aligned.m8n8.x4.trans.shared.b16 {%0,%1,%2,%3}, [%4];"
                 : "=r"(r[0]), "=r"(r[1]), "=r"(r[2]), "=r"(r[3]) : "r"(addr));
}

__device__ __forceinline__ void poll_ge(const unsigned* addr, unsigned target) {
    unsigned v;
    do {
        asm volatile("ld.acquire.gpu.global.u32 %0, [%1];" : "=r"(v) : "l"(addr));
    } while (v < target);
}

// swizzled h index (bf16 units)
__device__ __forceinline__ int hswz_idx(int j, int r) {
    return ((j >> 3) << 9) + ((j & 7) << 6) + (r ^ ((j & 7) << 3));
}

// ---------------------------------------------------------------------------
// Prep: transpose + gate-interleave + bf16 hi/lo split of the 4 gate weights.
// ---------------------------------------------------------------------------
__global__ void prep_weights(const float* __restrict__ Wf, const float* __restrict__ Wi,
                             const float* __restrict__ Wo, const float* __restrict__ Wg) {
    __shared__ float tile[32][33];
    const int g  = blockIdx.z;
    const float* W = (g == 0) ? Wf : (g == 1) ? Wi : (g == 2) ? Wo : Wg;
    const int k0 = blockIdx.x * 32;
    const int j0 = blockIdx.y * 32;
    const int tx = threadIdx.x & 31;
    const int ty = threadIdx.x >> 5;

    for (int r = ty; r < 32; r += 8)
        tile[r][tx] = W[(size_t)(k0 + r) * LAT + (j0 + tx)];
    __syncthreads();

    const bool isx = (k0 < DIM);
    for (int lj = ty; lj < 32; lj += 8) {
        float v = tile[tx][lj];
        __nv_bfloat16 hi = __float2bfloat16_rn(v);
        __nv_bfloat16 lo = __float2bfloat16_rn(v - __bfloat162float(hi));
        int p = 4 * (j0 + lj) + g;
        size_t idx = (size_t)p * 1024 + (size_t)(isx ? (k0 + tx) : (k0 + tx - DIM));
        if (isx) { g_Wxh[idx] = hi; g_Wxl[idx] = lo; }
        else     { g_Whh[idx] = hi; g_Whl[idx] = lo; }
    }
}

// Pack bias gate-interleaved; zero initial h (buffer 0) and c; reset barrier.
__global__ void pack_bias_zero(const float* __restrict__ bf, const float* __restrict__ bi,
                               const float* __restrict__ bo, const float* __restrict__ bg) {
    int i = blockIdx.x * blockDim.x + threadIdx.x;   // 65536 threads
    if (i < 8) g_ctr[i] = 0;
    if (i == 8) g_phase = 0;
    if (i < 4096) {
        int gs = i & 3, j = i >> 2;
        const float* b = (gs == 0) ? bf : (gs == 1) ? bi : (gs == 2) ? bo : bg;
        g_bias[i] = b[j];
    }
    if (i < 65536) {
        g_c[i]      = 0.0f;
        g_hsh[0][i] = __float2bfloat16_rn(0.0f);
        g_hsl[0][i] = __float2bfloat16_rn(0.0f);
    }
}

// Split x into bf16 hi/lo.
__global__ void split_x(const float* __restrict__ x) {
    size_t stride = (size_t)gridDim.x * blockDim.x;
    for (size_t i = (size_t)blockIdx.x * blockDim.x + threadIdx.x; i < 33554432u; i += stride) {
        float v = x[i];
        __nv_bfloat16 hi = __float2bfloat16_rn(v);
        g_xh[i] = hi;
        g_xl[i] = __float2bfloat16_rn(v - __bfloat162float(hi));
    }
}

// ---------------------------------------------------------------------------
// GEMM1: gates_x = x @ Wx_packed.  [unchanged from R8 — measured 2.09 ms]
// ---------------------------------------------------------------------------
typedef __nv_bfloat16 GTile[128][40];
#define GEMM_SMEM 81920

__global__ __launch_bounds__(256) void gemm_x() {
    extern __shared__ __align__(16) unsigned char gsm[];
    GTile* Ash = (GTile*)(gsm);
    GTile* Asl = (GTile*)(gsm + 20480);
    GTile* Bsh = (GTile*)(gsm + 40960);
    GTile* Bsl = (GTile*)(gsm + 61440);

    const int bm = blockIdx.x >> 5;
    const int bn = blockIdx.x & 31;
    const size_t gm0 = (size_t)bm * 128;
    const size_t gn0 = (size_t)bn * 128;

    const int lane = threadIdx.x & 31, wid = threadIdx.x >> 5;
    const int wm = wid >> 2, wn = wid & 3;
    const int gid = lane >> 2, tig = lane & 3;

    float C[4][4][4];
    #pragma unroll
    for (int a = 0; a < 4; ++a)
        #pragma unroll
        for (int b = 0; b < 4; ++b)
            #pragma unroll
            for (int c = 0; c < 4; ++c) C[a][b][c] = 0.0f;

    auto load_slab = [&](int st, int it) {
        const int k0 = it * 32;
        #pragma unroll
        for (int s = threadIdx.x; s < 512; s += 256) {
            int r = s >> 2, q = (s & 3) * 8;
            cp_async16(&Ash[st][r][q], g_xh  + (gm0 + r) * 1024 + k0 + q);
            cp_async16(&Asl[st][r][q], g_xl  + (gm0 + r) * 1024 + k0 + q);
            cp_async16(&Bsh[st][r][q], g_Wxh + (gn0 + r) * 1024 + k0 + q);
            cp_async16(&Bsl[st][r][q], g_Wxl + (gn0 + r) * 1024 + k0 + q);
        }
        cp_commit();
    };

    load_slab(0, 0);

    for (int it = 0; it < 32; ++it) {
        const int b = it & 1;
        if (it < 31) { load_slab(b ^ 1, it + 1); cp_wait1(); }
        else         { cp_wait0(); }
        __syncthreads();

        #pragma unroll
        for (int kk = 0; kk < 32; kk += 16) {
            const int cb = kk + 2 * tig;
            uint32_t ah[4][4], al[4][4], bh[4][2], bl[4][2];
            #pragma unroll
            for (int mt = 0; mt < 4; ++mt) {
                int row = wm * 64 + mt * 16 + gid;
                ah[mt][0] = *(const uint32_t*)&Ash[b][row    ][cb    ];
                ah[mt][1] = *(const uint32_t*)&Ash[b][row + 8][cb    ];
                ah[mt][2] = *(const uint32_t*)&Ash[b][row    ][cb + 8];
                ah[mt][3] = *(const uint32_t*)&Ash[b][row + 8][cb + 8];
                al[mt][0] = *(const uint32_t*)&Asl[b][row    ][cb    ];
                al[mt][1] = *(const uint32_t*)&Asl[b][row + 8][cb    ];
                al[mt][2] = *(const uint32_t*)&Asl[b][row    ][cb + 8];
                al[mt][3] = *(const uint32_t*)&Asl[b][row + 8][cb + 8];
            }
            #pragma unroll
            for (int nt = 0; nt < 4; ++nt) {
                int nr = wn * 32 + nt * 8 + gid;
                bh[nt][0] = *(const uint32_t*)&Bsh[b][nr][cb    ];
                bh[nt][1] = *(const uint32_t*)&Bsh[b][nr][cb + 8];
                bl[nt][0] = *(const uint32_t*)&Bsl[b][nr][cb    ];
                bl[nt][1] = *(const uint32_t*)&Bsl[b][nr][cb + 8];
            }
            #pragma unroll
            for (int mt = 0; mt < 4; ++mt)
                #pragma unroll
                for (int nt = 0; nt < 4; ++nt) {
                    mma_bf16(C[mt][nt], ah[mt], bh[nt]);
                    mma_bf16(C[mt][nt], ah[mt], bl[nt]);
                    mma_bf16(C[mt][nt], al[mt], bh[nt]);
                }
        }
        __syncthreads();
    }

    #pragma unroll
    for (int mt = 0; mt < 4; ++mt)
        #pragma unroll
        for (int nt = 0; nt < 4; ++nt) {
            size_t row = gm0 + wm * 64 + mt * 16 + gid;
            size_t col = gn0 + wn * 32 + nt * 8 + 2 * tig;
            *(float2*)&g_gx[row * 4096 + col]       = make_float2(C[mt][nt][0], C[mt][nt][1]);
            *(float2*)&g_gx[(row + 8) * 4096 + col] = make_float2(C[mt][nt][2], C[mt][nt][3]);
        }
}

// ---------------------------------------------------------------------------
// Persistent recurrent kernel. 128 CTAs x 256 thr (8 warps = 2 mt x 4 kh).
// h chunks (128 k = 16 KB contiguous in swizzled global) via cp.async.bulk +
// mbarrier (2-stage ring, 1-chunk lookahead ~= full-iter window); A-frags via
// ldmatrix.x4.trans; W resident in smem; split-counter grid barrier per step.
// ---------------------------------------------------------------------------
struct SmemLayout {
    __nv_bfloat16 Wh[32][1032];      //  66,048 B  (padded: conflict-free LDS.32)
    __nv_bfloat16 Wl[32][1032];      //  66,048
    __nv_bfloat16 Ah[2][8192];       //  32,768   2-stage h-hi chunks (128k, swizzled)
    __nv_bfloat16 Al[2][8192];       //  32,768   2-stage h-lo chunks
    float         red[2][3][32][33]; //  25,344   kh=1..3 partial staging
    unsigned long long full[2];      //  mbarriers
};
#define SMEM_BYTES sizeof(SmemLayout)
static_assert(sizeof(SmemLayout) <= 232448, "smem over budget");

// Split-counter grid barrier: spread arrivals over 8 counters, CTA0 aggregates.
__device__ __forceinline__ void grid_bar(unsigned step1) {   // step1 = t+1
    __syncthreads();
    if (threadIdx.x == 0) {
        __threadfence();
        atomicAdd(&g_ctr[blockIdx.x & 7], 1u);
        if (blockIdx.x == 0) {
            #pragma unroll
            for (int i = 0; i < 8; ++i) poll_ge(&g_ctr[i], 16u * step1);
            __threadfence();
            atomicAdd(&g_phase, 1u);
        } else {
            poll_ge(&g_phase, step1);
        }
    }
    __syncthreads();
}

__device__ __forceinline__ void lstm_update(int t, int r, int j,
                                            float pf, float pi, float po, float pg,
                                            int wb, float* __restrict__ out) {
    float f  = 1.0f / (1.0f + __expf(-pf));
    float ii = 1.0f / (1.0f + __expf(-pi));
    float o  = 1.0f / (1.0f + __expf(-po));
    float gg = tanhf(pg);
    int idx  = r * 1024 + j;
    float cn = f * g_c[idx] + ii * gg;
    g_c[idx] = cn;
    float h  = o * tanhf(cn);
    out[(size_t)t * 65536 + idx] = h;
    __nv_bfloat16 hi = __float2bfloat16_rn(h);
    int sidx = hswz_idx(j, r);
    g_hsh[wb][sidx] = hi;
    g_hsl[wb][sidx] = __float2bfloat16_rn(h - __bfloat162float(hi));
}

__global__ __launch_bounds__(256, 1) void lstm_persist(float* __restrict__ out) {
    extern __shared__ __align__(16) unsigned char smem_raw[];
    SmemLayout& S = *reinterpret_cast<SmemLayout*>(smem_raw);
    const uint32_t sbase = (uint32_t)__cvta_generic_to_shared(smem_raw);
    const uint32_t ahOff = (uint32_t)((char*)&S.Ah[0][0] - (char*)&S);
    const uint32_t alOff = (uint32_t)((char*)&S.Al[0][0] - (char*)&S);
    const uint32_t mbOff = (uint32_t)((char*)&S.full[0]  - (char*)&S);

    const int tid  = threadIdx.x;
    const int lane = tid & 31, wid = tid >> 5;   // 8 warps
    const int mt = wid & 1;                      // 2 row groups (32 rows each)
    const int kh = wid >> 1;                     // 4 K-quarters per 128-chunk
    const int g8 = lane >> 2, tig = lane & 3;
    const int P0 = blockIdx.x * 32;

    // One-time weight slice load (128 KB resident).
    for (int s = tid; s < 4096; s += 256) {
        int r = s >> 7, q = (s & 127) * 8;
        *(uint4*)&S.Wh[r][q] = *(const uint4*)(g_Whh + (size_t)(P0 + r) * 1024 + q);
        *(uint4*)&S.Wl[r][q] = *(const uint4*)(g_Whl + (size_t)(P0 + r) * 1024 + q);
    }
    if (tid == 0) { mbar_init(sbase + mbOff, 1); mbar_init(sbase + mbOff + 8, 1); }
    __syncthreads();

    // ldmatrix lane addressing (R11-proven): tiles (k,r),(k,r+8),(k+8,r),(k+8,r+8)
    const int lK = (lane & 7) + ((lane & 16) ? 8 : 0);
    const int lR = (lane & 8) ? 8 : 0;

    // epilogue constants (kh==0 warps)
    int pcol[4];  float vb[4][2];
    #pragma unroll
    for (int nb = 0; nb < 4; ++nb) {
        pcol[nb] = P0 + nb * 8 + 2 * tig;
        vb[nb][0] = g_bias[pcol[nb]];
        vb[nb][1] = g_bias[pcol[nb] + 1];
    }

    for (int t = 0; t < T_SEQ; ++t) {
        const int rb = t & 1, wb = rb ^ 1;
        const char* hs = (const char*)g_hsh[rb];
        const char* ls = (const char*)g_hsl[rb];
        const float* __restrict__ gx = g_gx + (size_t)t * BATCH * 4096;

        // Prefetch gates_x operands (kh==0 warps; streaming).
        float2 vg[2][4][2];
        if (kh == 0) {
            #pragma unroll
            for (int mtile = 0; mtile < 2; ++mtile) {
                int r = mt * 32 + mtile * 16 + g8;
                #pragma unroll
                for (int nb = 0; nb < 4; ++nb) {
                    int p = pcol[nb];
                    vg[mtile][nb][0] = __ldcs((const float2*)&gx[(size_t)r * 4096 + p]);
                    vg[mtile][nb][1] = __ldcs((const float2*)&gx[(size_t)(r + 8) * 4096 + p]);
                }
            }
        }

        float C[2][4][4];
        #pragma unroll
        for (int a = 0; a < 2; ++a)
            #pragma unroll
            for (int b = 0; b < 4; ++b)
                #pragma unroll
                for (int c = 0; c < 4; ++c) C[a][b][c] = 0.0f;

        // preload chunk 0 (stage 0): 2 bulk copies of 16 KB
        if (tid == 0) {
            mbar_expect_tx(sbase + mbOff, 32768);
            bulk_g2s(sbase + ahOff, hs, 16384, sbase + mbOff);
            bulk_g2s(sbase + alOff, ls, 16384, sbase + mbOff);
        }

        for (int it = 0; it < 8; ++it) {
            if (it < 7 && tid == 0) {           // refill freed stage (chunk it+1)
                const int s = (it + 1) & 1;
                mbar_expect_tx(sbase + mbOff + 8 * s, 32768);
                bulk_g2s(sbase + ahOff + s * 16384, hs + (it + 1) * 16384, 16384,
                         sbase + mbOff + 8 * s);
                bulk_g2s(sbase + alOff + s * 16384, ls + (it + 1) * 16384, 16384,
                         sbase + mbOff + 8 * s);
            }
            const int b = it & 1;
            mbar_wait(sbase + mbOff + 8 * b, (it >> 1) & 1);

            #pragma unroll
            for (int kk2 = 0; kk2 < 64; kk2 += 16) {     // kh covers 32k; 2 k-steps
                const int kRow = kh * 32 + (kk2 >> 1) + lK;   // kk2/2 in {0,16}? no:
                // kh quarter spans 32 k: k-steps at kh*32 + {0,16}
                (void)kRow;
            }
            #pragma unroll
            for (int ks = 0; ks < 2; ++ks) {
                const int kbase = kh * 32 + ks * 16;     // k within 128-chunk
                const int kRow  = kbase + lK;
                uint32_t abyte = ((uint32_t)(kRow >> 3) << 10) + ((uint32_t)(kRow & 7) << 7);
                uint32_t ah[2][4], al[2][4];
                #pragma unroll
                for (int mtile = 0; mtile < 2; ++mtile) {
                    int rOff = mt * 32 + mtile * 16 + lR;
                    uint32_t boff = abyte +
                        (((uint32_t)rOff << 1) ^ ((uint32_t)(kRow & 7) << 4));
                    ldmatrix_x4_trans(ah[mtile], sbase + ahOff + b * 16384 + boff);
                    ldmatrix_x4_trans(al[mtile], sbase + alOff + b * 16384 + boff);
                }
                const int cw = it * 128 + kbase + 2 * tig;   // global k (W resident)
                #pragma unroll
                for (int nb = 0; nb < 4; ++nb) {
                    int nr = nb * 8 + g8;
                    uint32_t bh[2], bl[2];
                    bh[0] = *(const uint32_t*)&S.Wh[nr][cw    ];
                    bh[1] = *(const uint32_t*)&S.Wh[nr][cw + 8];
                    bl[0] = *(const uint32_t*)&S.Wl[nr][cw    ];
                    bl[1] = *(const uint32_t*)&S.Wl[nr][cw + 8];
                    #pragma unroll
                    for (int mtile = 0; mtile < 2; ++mtile) {
                        mma_bf16(C[mtile][nb], ah[mtile], bh);
                        mma_bf16(C[mtile][nb], ah[mtile], bl);
                        mma_bf16(C[mtile][nb], al[mtile], bh);
                    }
                }
            }
            __syncthreads();                     // all warps done with stage b
        }

        // K-split reduction: kh=1..3 stage partials; kh=0 adds.  [proven]
        if (kh > 0) {
            float* dst = &S.red[mt][kh - 1][lane][0];
            #pragma unroll
            for (int mtile = 0; mtile < 2; ++mtile)
                #pragma unroll
                for (int nb = 0; nb < 4; ++nb)
                    #pragma unroll
                    for (int i = 0; i < 4; ++i)
                        dst[mtile * 16 + nb * 4 + i] = C[mtile][nb][i];
        }
        __syncthreads();

        if (kh == 0) {
            #pragma unroll
            for (int s = 0; s < 3; ++s) {
                const float* src = &S.red[mt][s][lane][0];
                #pragma unroll
                for (int mtile = 0; mtile < 2; ++mtile)
                    #pragma unroll
                    for (int nb = 0; nb < 4; ++nb)
                        #pragma unroll
                        for (int i = 0; i < 4; ++i)
                            C[mtile][nb][i] += src[mtile * 16 + nb * 4 + i];
            }
            // Epilogue: add x-part + bias, pair-exchange (f,i)<->(o,g), update.
            #pragma unroll
            for (int mtile = 0; mtile < 2; ++mtile) {
                int r = mt * 32 + mtile * 16 + g8;
                #pragma unroll
                for (int nb = 0; nb < 4; ++nb) {
                    float v0 = C[mtile][nb][0] + vg[mtile][nb][0].x + vb[nb][0];
                    float v1 = C[mtile][nb][1] + vg[mtile][nb][0].y + vb[nb][1];
                    float v2 = C[mtile][nb][2] + vg[mtile][nb][1].x + vb[nb][0];
                    float v3 = C[mtile][nb][3] + vg[mtile][nb][1].y + vb[nb][1];
                    float q0 = __shfl_xor_sync(0xffffffffu, v0, 1);
                    float q1 = __shfl_xor_sync(0xffffffffu, v1, 1);
                    float q2 = __shfl_xor_sync(0xffffffffu, v2, 1);
                    float q3 = __shfl_xor_sync(0xffffffffu, v3, 1);
                    if ((lane & 1) == 0) {       // holds (f,i); partner held (o,g)
                        int j = pcol[nb] >> 2;
                        lstm_update(t, r,     j, v0, v1, q0, q1, wb, out);
                        lstm_update(t, r + 8, j, v2, v3, q2, q3, wb, out);
                    }
                }
            }
        }

        if (t < T_SEQ - 1) grid_bar((unsigned)(t + 1));
    }
}

// ---------------------------------------------------------------------------
// Launch: default stream, fully capturable; one persistent recurrent kernel.
// ---------------------------------------------------------------------------
extern "C" void kernel_launch(void* const* d_in, const int* in_sizes, int n_in,
                              void* d_out, int out_size) {
    const float* x  = (const float*)d_in[0];
    const float* Wf = (const float*)d_in[1];
    const float* bf = (const float*)d_in[2];
    const float* Wi = (const float*)d_in[3];
    const float* bi = (const float*)d_in[4];
    const float* Wo = (const float*)d_in[5];
    const float* bo = (const float*)d_in[6];
    const float* Wg = (const float*)d_in[7];
    const float* bg = (const float*)d_in[8];
    float* out = (float*)d_out;

    cudaFuncSetAttribute(gemm_x, cudaFuncAttributeMaxDynamicSharedMemorySize,
                         GEMM_SMEM);
    cudaFuncSetAttribute(lstm_persist, cudaFuncAttributeMaxDynamicSharedMemorySize,
                         (int)SMEM_BYTES);

    prep_weights<<<dim3(64, 32, 4), 256>>>(Wf, Wi, Wo, Wg);
    pack_bias_zero<<<256, 256>>>(bf, bi, bo, bg);
    split_x<<<8192, 256>>>(x);
    gemm_x<<<8192, 256, GEMM_SMEM>>>();
    lstm_persist<<<NCTA, 256, SMEM_BYTES>>>(out);
}

// round 14
// speedup vs baseline: 1.0729x; 1.0729x over previous
#include <cuda_runtime.h>
#include <cuda_bf16.h>
#include <stdint.h>

// Problem constants
#define T_SEQ 512
#define BATCH 64
#define DIM   1024
#define LAT   1024
#define NPACK 4096            // 4*LAT, gate-interleaved packed columns: p = 4*j + g
#define M1    32768           // T_SEQ*BATCH
#define NCTA  128             // persistent grid (<=148 SMs, 1 CTA/SM by smem)

// ---------------------------------------------------------------------------
// Device scratch (static __device__ arrays; no allocations anywhere)
// ---------------------------------------------------------------------------
__device__ float          g_gx[134217728];          // [M1][NPACK] fp32 x-part gates (512 MB)
__device__ __nv_bfloat16  g_Wxh[4194304], g_Wxl[4194304];  // Wx packed [NPACK][DIM] hi/lo
__device__ __nv_bfloat16  g_Whh[4194304], g_Whl[4194304];  // Wh packed [NPACK][LAT] hi/lo
__device__ __nv_bfloat16  g_xh[33554432], g_xl[33554432];  // x split   [M1][DIM]    hi/lo
__device__ __nv_bfloat16  g_hh[2][65536], g_hl[2][65536];  // h state double-buffered, bf16 hi/lo
__device__ float          g_c[65536];                       // c state fp32
__device__ float          g_bias[4096];                     // packed bias
__device__ unsigned       g_ctr[8];                         // spread arrival counters
__device__ unsigned       g_phase;                          // barrier phase broadcast

// ---------------------------------------------------------------------------
// mma.sync m16n8k16 bf16 helper (fp32 accumulate)
// ---------------------------------------------------------------------------
__device__ __forceinline__ void mma_bf16(float c[4], const uint32_t a[4], const uint32_t b[2]) {
    asm volatile(
        "mma.sync.aligned.m16n8k16.row.col.f32.bf16.bf16.f32 "
        "{%0,%1,%2,%3}, {%4,%5,%6,%7}, {%8,%9}, {%0,%1,%2,%3};\n"
        : "+f"(c[0]), "+f"(c[1]), "+f"(c[2]), "+f"(c[3])
        : "r"(a[0]), "r"(a[1]), "r"(a[2]), "r"(a[3]), "r"(b[0]), "r"(b[1]));
}

// cp.async helpers (16B, L2-only path: .cg)
__device__ __forceinline__ void cp_async16(void* sptr, const void* gptr) {
    uint32_t s = (uint32_t)__cvta_generic_to_shared(sptr);
    asm volatile("cp.async.cg.shared.global [%0], [%1], 16;\n" :: "r"(s), "l"(gptr));
}
__device__ __forceinline__ void cp_commit() { asm volatile("cp.async.commit_group;\n"); }
__device__ __forceinline__ void cp_wait1()  { asm volatile("cp.async.wait_group 1;\n"); }
__device__ __forceinline__ void cp_wait0()  { asm volatile("cp.async.wait_group 0;\n"); }

__device__ __forceinline__ void poll_ge(const unsigned* addr, unsigned target) {
    unsigned v;
    do {
        asm volatile("ld.acquire.gpu.global.u32 %0, [%1];" : "=r"(v) : "l"(addr));
    } while (v < target);
}

// ---------------------------------------------------------------------------
// Prep: transpose + gate-interleave + bf16 hi/lo split of the 4 gate weights.
// Source W_g is [D+L, L] row-major. Dest: n-major [p][k]. p = 4*j + g.
// ---------------------------------------------------------------------------
__global__ void prep_weights(const float* __restrict__ Wf, const float* __restrict__ Wi,
                             const float* __restrict__ Wo, const float* __restrict__ Wg) {
    __shared__ float tile[32][33];
    const int g  = blockIdx.z;
    const float* W = (g == 0) ? Wf : (g == 1) ? Wi : (g == 2) ? Wo : Wg;
    const int k0 = blockIdx.x * 32;     // 0..2047 (k index in D+L)
    const int j0 = blockIdx.y * 32;     // 0..1023
    const int tx = threadIdx.x & 31;
    const int ty = threadIdx.x >> 5;    // 0..7

    for (int r = ty; r < 32; r += 8)
        tile[r][tx] = W[(size_t)(k0 + r) * LAT + (j0 + tx)];
    __syncthreads();

    const bool isx = (k0 < DIM);
    for (int lj = ty; lj < 32; lj += 8) {
        float v = tile[tx][lj];                                   // (k0+tx, j0+lj)
        __nv_bfloat16 hi = __float2bfloat16_rn(v);
        __nv_bfloat16 lo = __float2bfloat16_rn(v - __bfloat162float(hi));
        int p = 4 * (j0 + lj) + g;
        size_t idx = (size_t)p * 1024 + (size_t)(isx ? (k0 + tx) : (k0 + tx - DIM));
        if (isx) { g_Wxh[idx] = hi; g_Wxl[idx] = lo; }
        else     { g_Whh[idx] = hi; g_Whl[idx] = lo; }
    }
}

// Pack bias gate-interleaved; zero initial h (buffer 0) and c; reset barrier.
__global__ void pack_bias_zero(const float* __restrict__ bf, const float* __restrict__ bi,
                               const float* __restrict__ bo, const float* __restrict__ bg) {
    int i = blockIdx.x * blockDim.x + threadIdx.x;   // 65536 threads
    if (i < 8) g_ctr[i] = 0;
    if (i == 8) g_phase = 0;
    if (i < 4096) {
        int gs = i & 3, j = i >> 2;
        const float* b = (gs == 0) ? bf : (gs == 1) ? bi : (gs == 2) ? bo : bg;
        g_bias[i] = b[j];
    }
    if (i < 65536) {
        g_c[i]     = 0.0f;
        g_hh[0][i] = __float2bfloat16_rn(0.0f);
        g_hl[0][i] = __float2bfloat16_rn(0.0f);
    }
}

// Split x into bf16 hi/lo.
__global__ void split_x(const float* __restrict__ x) {
    size_t stride = (size_t)gridDim.x * blockDim.x;
    for (size_t i = (size_t)blockIdx.x * blockDim.x + threadIdx.x; i < 33554432u; i += stride) {
        float v = x[i];
        __nv_bfloat16 hi = __float2bfloat16_rn(v);
        g_xh[i] = hi;
        g_xl[i] = __float2bfloat16_rn(v - __bfloat162float(hi));
    }
}

// ---------------------------------------------------------------------------
// GEMM1: gates_x[M1, NPACK] = x[M1, DIM] @ Wx_packed[DIM, NPACK]
// 3xbf16 error-compensated: C = Ah*Bh + Ah*Bl + Al*Bh, fp32 accum.
// CTA tile 128x128, BK=32, 256 threads / 8 warps (2m x 4n), warp tile 64x32.
// 2-stage cp.async pipeline (dynamic smem, 80 KB/CTA).  [R7-proven: 2.09 ms]
// ---------------------------------------------------------------------------
typedef __nv_bfloat16 GTile[128][40];     // 10240 B
#define GEMM_SMEM 81920                   // 8 tiles (4 arrays x 2 stages)

__global__ __launch_bounds__(256) void gemm_x() {
    extern __shared__ __align__(16) unsigned char gsm[];
    GTile* Ash = (GTile*)(gsm);               // [2]
    GTile* Asl = (GTile*)(gsm + 20480);       // [2]
    GTile* Bsh = (GTile*)(gsm + 40960);       // [2]
    GTile* Bsl = (GTile*)(gsm + 61440);       // [2]

    const int bm = blockIdx.x >> 5;          // 0..255
    const int bn = blockIdx.x & 31;          // 0..31   (n fastest: B tiles stay L2-hot)
    const size_t gm0 = (size_t)bm * 128;
    const size_t gn0 = (size_t)bn * 128;

    const int lane = threadIdx.x & 31, wid = threadIdx.x >> 5;
    const int wm = wid >> 2, wn = wid & 3;
    const int gid = lane >> 2, tig = lane & 3;

    float C[4][4][4];
    #pragma unroll
    for (int a = 0; a < 4; ++a)
        #pragma unroll
        for (int b = 0; b < 4; ++b)
            #pragma unroll
            for (int c = 0; c < 4; ++c) C[a][b][c] = 0.0f;

    auto load_slab = [&](int st, int it) {
        const int k0 = it * 32;
        #pragma unroll
        for (int s = threadIdx.x; s < 512; s += 256) {
            int r = s >> 2, q = (s & 3) * 8;
            cp_async16(&Ash[st][r][q], g_xh  + (gm0 + r) * 1024 + k0 + q);
            cp_async16(&Asl[st][r][q], g_xl  + (gm0 + r) * 1024 + k0 + q);
            cp_async16(&Bsh[st][r][q], g_Wxh + (gn0 + r) * 1024 + k0 + q);
            cp_async16(&Bsl[st][r][q], g_Wxl + (gn0 + r) * 1024 + k0 + q);
        }
        cp_commit();
    };

    load_slab(0, 0);

    for (int it = 0; it < 32; ++it) {
        const int b = it & 1;
        if (it < 31) { load_slab(b ^ 1, it + 1); cp_wait1(); }
        else         { cp_wait0(); }
        __syncthreads();

        #pragma unroll
        for (int kk = 0; kk < 32; kk += 16) {
            const int cb = kk + 2 * tig;
            uint32_t ah[4][4], al[4][4], bh[4][2], bl[4][2];
            #pragma unroll
            for (int mt = 0; mt < 4; ++mt) {
                int row = wm * 64 + mt * 16 + gid;
                ah[mt][0] = *(const uint32_t*)&Ash[b][row    ][cb    ];
                ah[mt][1] = *(const uint32_t*)&Ash[b][row + 8][cb    ];
                ah[mt][2] = *(const uint32_t*)&Ash[b][row    ][cb + 8];
                ah[mt][3] = *(const uint32_t*)&Ash[b][row + 8][cb + 8];
                al[mt][0] = *(const uint32_t*)&Asl[b][row    ][cb    ];
                al[mt][1] = *(const uint32_t*)&Asl[b][row + 8][cb    ];
                al[mt][2] = *(const uint32_t*)&Asl[b][row    ][cb + 8];
                al[mt][3] = *(const uint32_t*)&Asl[b][row + 8][cb + 8];
            }
            #pragma unroll
            for (int nt = 0; nt < 4; ++nt) {
                int nr = wn * 32 + nt * 8 + gid;
                bh[nt][0] = *(const uint32_t*)&Bsh[b][nr][cb    ];
                bh[nt][1] = *(const uint32_t*)&Bsh[b][nr][cb + 8];
                bl[nt][0] = *(const uint32_t*)&Bsl[b][nr][cb    ];
                bl[nt][1] = *(const uint32_t*)&Bsl[b][nr][cb + 8];
            }
            #pragma unroll
            for (int mt = 0; mt < 4; ++mt)
                #pragma unroll
                for (int nt = 0; nt < 4; ++nt) {
                    mma_bf16(C[mt][nt], ah[mt], bh[nt]);
                    mma_bf16(C[mt][nt], ah[mt], bl[nt]);
                    mma_bf16(C[mt][nt], al[mt], bh[nt]);
                }
        }
        __syncthreads();
    }

    #pragma unroll
    for (int mt = 0; mt < 4; ++mt)
        #pragma unroll
        for (int nt = 0; nt < 4; ++nt) {
            size_t row = gm0 + wm * 64 + mt * 16 + gid;
            size_t col = gn0 + wn * 32 + nt * 8 + 2 * tig;
            *(float2*)&g_gx[row * 4096 + col]       = make_float2(C[mt][nt][0], C[mt][nt][1]);
            *(float2*)&g_gx[(row + 8) * 4096 + col] = make_float2(C[mt][nt][2], C[mt][nt][3]);
        }
}

// ---------------------------------------------------------------------------
// Persistent recurrent kernel — R7 VERBATIM except the grid barrier.
// 128 CTAs x 256 thr (8 warps = 4 mt x 2 nh); W resident in smem; h streamed
// per step via 16B cp.async double buffer (K-chunk 128); one split-counter
// grid barrier per step; h double-buffered.
// ---------------------------------------------------------------------------
struct SmemLayout {
    __nv_bfloat16 Wh[32][1032];     // padded stride: conflict-free frags
    __nv_bfloat16 Wl[32][1032];
    __nv_bfloat16 Ah[2][64][136];   // K-chunk 128, double buffered
    __nv_bfloat16 Al[2][64][136];
};
#define SMEM_BYTES sizeof(SmemLayout)   // 201728 B

// Split-counter grid barrier: arrivals spread over 8 words (16 CTAs each),
// CTA0 aggregates and bumps the phase word everyone else polls.
__device__ __forceinline__ void grid_bar(unsigned step1) {   // step1 = t+1
    __syncthreads();
    if (threadIdx.x == 0) {
        __threadfence();
        atomicAdd(&g_ctr[blockIdx.x & 7], 1u);
        if (blockIdx.x == 0) {
            #pragma unroll
            for (int i = 0; i < 8; ++i) poll_ge(&g_ctr[i], 16u * step1);
            __threadfence();
            atomicAdd(&g_phase, 1u);
        } else {
            poll_ge(&g_phase, step1);
        }
    }
    __syncthreads();
}

__device__ __forceinline__ void lstm_update(int t, int r, int j,
                                            float pf, float pi, float po, float pg,
                                            int wb, float* __restrict__ out) {
    float f  = 1.0f / (1.0f + __expf(-pf));
    float ii = 1.0f / (1.0f + __expf(-pi));
    float o  = 1.0f / (1.0f + __expf(-po));
    float gg = tanhf(pg);
    int idx  = r * 1024 + j;
    float cn = f * g_c[idx] + ii * gg;
    g_c[idx] = cn;
    float h  = o * tanhf(cn);
    out[(size_t)t * 65536 + idx] = h;
    __nv_bfloat16 hi = __float2bfloat16_rn(h);
    g_hh[wb][idx] = hi;
    g_hl[wb][idx] = __float2bfloat16_rn(h - __bfloat162float(hi));
}

__global__ __launch_bounds__(256, 1) void lstm_persist(float* __restrict__ out) {
    extern __shared__ __align__(16) unsigned char smem_raw[];
    SmemLayout& S = *reinterpret_cast<SmemLayout*>(smem_raw);

    const int tid  = threadIdx.x;
    const int lane = tid & 31, wid = tid >> 5;
    const int mt = wid & 3, nh = wid >> 2;       // warp tile: rows 16*mt, cols 16*nh
    const int g8  = lane >> 2, tig = lane & 3;
    const int P0  = blockIdx.x * 32;
    const int row = mt * 16 + g8;

    // One-time weight slice load: 32 rows x 1024 k, hi+lo (128 KB) into smem.
    for (int s = tid; s < 4096; s += 256) {
        int r = s >> 7, q = (s & 127) * 8;
        *(uint4*)&S.Wh[r][q] = *(const uint4*)(g_Whh + (size_t)(P0 + r) * 1024 + q);
        *(uint4*)&S.Wl[r][q] = *(const uint4*)(g_Whl + (size_t)(P0 + r) * 1024 + q);
    }
    __syncthreads();

    // Loop-invariant: packed columns + bias for this thread's epilogue.
    int pcol[2];  float vb[2][2];
    #pragma unroll
    for (int nb = 0; nb < 2; ++nb) {
        pcol[nb] = P0 + nh * 16 + nb * 8 + 2 * tig;
        vb[nb][0] = g_bias[pcol[nb]];
        vb[nb][1] = g_bias[pcol[nb] + 1];
    }

    for (int t = 0; t < T_SEQ; ++t) {
        const int rb = t & 1, wb = rb ^ 1;
        const __nv_bfloat16* __restrict__ hh = g_hh[rb];
        const __nv_bfloat16* __restrict__ hl = g_hl[rb];
        const float* __restrict__ gx = g_gx + (size_t)t * BATCH * 4096;

        // Prefetch this thread's gates_x operands (streaming; hidden by compute).
        float2 vg[2][2];
        #pragma unroll
        for (int nb = 0; nb < 2; ++nb) {
            int p = pcol[nb];
            vg[nb][0] = __ldcs((const float2*)&gx[(size_t)row * 4096 + p]);
            vg[nb][1] = __ldcs((const float2*)&gx[(size_t)(row + 8) * 4096 + p]);
        }

        float C[2][4] = {};

        // Preload chunk 0 of h (hi+lo).
        for (int s = tid; s < 1024; s += 256) {
            int r = s >> 4, q = (s & 15) * 8;
            cp_async16(&S.Ah[0][r][q], hh + r * 1024 + q);
            cp_async16(&S.Al[0][r][q], hl + r * 1024 + q);
        }
        cp_commit();

        for (int it = 0; it < 8; ++it) {
            if (it < 7) {
                const int k0 = (it + 1) * 128, b = (it + 1) & 1;
                for (int s = tid; s < 1024; s += 256) {
                    int r = s >> 4, q = (s & 15) * 8;
                    cp_async16(&S.Ah[b][r][q], hh + r * 1024 + k0 + q);
                    cp_async16(&S.Al[b][r][q], hl + r * 1024 + k0 + q);
                }
                cp_commit();
                cp_wait1();
            } else {
                cp_wait0();
            }
            __syncthreads();
            const int b = it & 1;
            #pragma unroll
            for (int kk = 0; kk < 128; kk += 16) {
                const int ca = kk + 2 * tig;          // k within chunk (A)
                const int cw = it * 128 + ca;         // global k (W, fully resident)
                uint32_t ah[4], al[4];
                ah[0] = *(const uint32_t*)&S.Ah[b][row    ][ca    ];
                ah[1] = *(const uint32_t*)&S.Ah[b][row + 8][ca    ];
                ah[2] = *(const uint32_t*)&S.Ah[b][row    ][ca + 8];
                ah[3] = *(const uint32_t*)&S.Ah[b][row + 8][ca + 8];
                al[0] = *(const uint32_t*)&S.Al[b][row    ][ca    ];
                al[1] = *(const uint32_t*)&S.Al[b][row + 8][ca    ];
                al[2] = *(const uint32_t*)&S.Al[b][row    ][ca + 8];
                al[3] = *(const uint32_t*)&S.Al[b][row + 8][ca + 8];
                #pragma unroll
                for (int nb = 0; nb < 2; ++nb) {
                    const int nr = nh * 16 + nb * 8 + g8;
                    uint32_t bh[2], bl[2];
                    bh[0] = *(const uint32_t*)&S.Wh[nr][cw    ];
                    bh[1] = *(const uint32_t*)&S.Wh[nr][cw + 8];
                    bl[0] = *(const uint32_t*)&S.Wl[nr][cw    ];
                    bl[1] = *(const uint32_t*)&S.Wl[nr][cw + 8];
                    mma_bf16(C[nb], ah, bh);
                    mma_bf16(C[nb], ah, bl);
                    mma_bf16(C[nb], al, bh);
                }
            }
            __syncthreads();
        }

        // Epilogue: add x-part + bias, pair-exchange (f,i)<->(o,g), update cell.
        #pragma unroll
        for (int nb = 0; nb < 2; ++nb) {
            float v0 = C[nb][0] + vg[nb][0].x + vb[nb][0];
            float v1 = C[nb][1] + vg[nb][0].y + vb[nb][1];
            float v2 = C[nb][2] + vg[nb][1].x + vb[nb][0];
            float v3 = C[nb][3] + vg[nb][1].y + vb[nb][1];
            float q0 = __shfl_xor_sync(0xffffffffu, v0, 1);
            float q1 = __shfl_xor_sync(0xffffffffu, v1, 1);
            float q2 = __shfl_xor_sync(0xffffffffu, v2, 1);
            float q3 = __shfl_xor_sync(0xffffffffu, v3, 1);
            if ((lane & 1) == 0) {               // holds (f,i); partner held (o,g)
                int j = pcol[nb] >> 2;
                lstm_update(t, row,     j, v0, v1, q0, q1, wb, out);
                lstm_update(t, row + 8, j, v2, v3, q2, q3, wb, out);
            }
        }

        if (t < T_SEQ - 1) grid_bar((unsigned)(t + 1));
    }
}

// ---------------------------------------------------------------------------
// Launch: default stream, fully capturable; one persistent recurrent kernel.
// ---------------------------------------------------------------------------
extern "C" void kernel_launch(void* const* d_in, const int* in_sizes, int n_in,
                              void* d_out, int out_size) {
    const float* x  = (const float*)d_in[0];
    const float* Wf = (const float*)d_in[1];
    const float* bf = (const float*)d_in[2];
    const float* Wi = (const float*)d_in[3];
    const float* bi = (const float*)d_in[4];
    const float* Wo = (const float*)d_in[5];
    const float* bo = (const float*)d_in[6];
    const float* Wg = (const float*)d_in[7];
    const float* bg = (const float*)d_in[8];
    float* out = (float*)d_out;

    cudaFuncSetAttribute(gemm_x, cudaFuncAttributeMaxDynamicSharedMemorySize,
                         GEMM_SMEM);
    cudaFuncSetAttribute(lstm_persist, cudaFuncAttributeMaxDynamicSharedMemorySize,
                         (int)SMEM_BYTES);

    prep_weights<<<dim3(64, 32, 4), 256>>>(Wf, Wi, Wo, Wg);
    pack_bias_zero<<<256, 256>>>(bf, bi, bo, bg);
    split_x<<<8192, 256>>>(x);
    gemm_x<<<8192, 256, GEMM_SMEM>>>();
    lstm_persist<<<NCTA, 256, SMEM_BYTES>>>(out);
}

// round 15
// speedup vs baseline: 1.3964x; 1.3015x over previous
#include <cuda_runtime.h>
#include <cuda_bf16.h>
#include <cuda_fp16.h>
#include <stdint.h>

// Problem constants
#define T_SEQ 512
#define BATCH 64
#define DIM   1024
#define LAT   1024
#define NPACK 4096            // 4*LAT, gate-interleaved packed columns: p = 4*j + g
#define M1    32768           // T_SEQ*BATCH
#define NCTA  128             // persistent grid (<=148 SMs, 1 CTA/SM by smem)

// ---------------------------------------------------------------------------
// Device scratch (static __device__ arrays; no allocations anywhere)
// ---------------------------------------------------------------------------
__device__ float          g_gx[134217728];          // [M1][NPACK] fp32 x-part gates (512 MB)
__device__ __nv_bfloat16  g_Wxh[4194304], g_Wxl[4194304];  // Wx packed [NPACK][DIM] bf16 hi/lo
__device__ __half         g_Whh[4194304], g_Whl[4194304];  // Wh packed [NPACK][LAT] fp16 hi/lo
__device__ __nv_bfloat16  g_xh[33554432], g_xl[33554432];  // x split   [M1][DIM]    bf16 hi/lo
__device__ __half         g_hh[2][65536];                  // h state double-buffered, fp16
__device__ float          g_c[65536];                       // c state fp32
__device__ float          g_bias[4096];                     // packed bias
__device__ unsigned       g_bar_count;                      // central grid barrier (R7-proven)
__device__ unsigned       g_bar_phase;

// ---------------------------------------------------------------------------
// mma.sync m16n8k16 helpers (fp32 accumulate)
// ---------------------------------------------------------------------------
__device__ __forceinline__ void mma_bf16(float c[4], const uint32_t a[4], const uint32_t b[2]) {
    asm volatile(
        "mma.sync.aligned.m16n8k16.row.col.f32.bf16.bf16.f32 "
        "{%0,%1,%2,%3}, {%4,%5,%6,%7}, {%8,%9}, {%0,%1,%2,%3};\n"
        : "+f"(c[0]), "+f"(c[1]), "+f"(c[2]), "+f"(c[3])
        : "r"(a[0]), "r"(a[1]), "r"(a[2]), "r"(a[3]), "r"(b[0]), "r"(b[1]));
}
__device__ __forceinline__ void mma_f16(float c[4], const uint32_t a[4], const uint32_t b[2]) {
    asm volatile(
        "mma.sync.aligned.m16n8k16.row.col.f32.f16.f16.f32 "
        "{%0,%1,%2,%3}, {%4,%5,%6,%7}, {%8,%9}, {%0,%1,%2,%3};\n"
        : "+f"(c[0]), "+f"(c[1]), "+f"(c[2]), "+f"(c[3])
        : "r"(a[0]), "r"(a[1]), "r"(a[2]), "r"(a[3]), "r"(b[0]), "r"(b[1]));
}

// cp.async helpers (16B, L2-only path: .cg)
__device__ __forceinline__ void cp_async16(void* sptr, const void* gptr) {
    uint32_t s = (uint32_t)__cvta_generic_to_shared(sptr);
    asm volatile("cp.async.cg.shared.global [%0], [%1], 16;\n" :: "r"(s), "l"(gptr));
}
__device__ __forceinline__ void cp_commit() { asm volatile("cp.async.commit_group;\n"); }
__device__ __forceinline__ void cp_wait1()  { asm volatile("cp.async.wait_group 1;\n"); }
__device__ __forceinline__ void cp_wait0()  { asm volatile("cp.async.wait_group 0;\n"); }

// ---------------------------------------------------------------------------
// Prep: transpose + gate-interleave + split of the 4 gate weights.
// x-rows (k<DIM)  -> bf16 hi/lo (exact 3-term path in gemm_x)
// h-rows (k>=DIM) -> fp16 hi/lo (2-term path in lstm_persist)
// ---------------------------------------------------------------------------
__global__ void prep_weights(const float* __restrict__ Wf, const float* __restrict__ Wi,
                             const float* __restrict__ Wo, const float* __restrict__ Wg) {
    __shared__ float tile[32][33];
    const int g  = blockIdx.z;
    const float* W = (g == 0) ? Wf : (g == 1) ? Wi : (g == 2) ? Wo : Wg;
    const int k0 = blockIdx.x * 32;     // 0..2047 (k index in D+L)
    const int j0 = blockIdx.y * 32;     // 0..1023
    const int tx = threadIdx.x & 31;
    const int ty = threadIdx.x >> 5;    // 0..7

    for (int r = ty; r < 32; r += 8)
        tile[r][tx] = W[(size_t)(k0 + r) * LAT + (j0 + tx)];
    __syncthreads();

    const bool isx = (k0 < DIM);
    for (int lj = ty; lj < 32; lj += 8) {
        float v = tile[tx][lj];                                   // (k0+tx, j0+lj)
        int p = 4 * (j0 + lj) + g;
        if (isx) {
            __nv_bfloat16 hi = __float2bfloat16_rn(v);
            __nv_bfloat16 lo = __float2bfloat16_rn(v - __bfloat162float(hi));
            size_t idx = (size_t)p * 1024 + (size_t)(k0 + tx);
            g_Wxh[idx] = hi; g_Wxl[idx] = lo;
        } else {
            __half hi = __float2half_rn(v);
            __half lo = __float2half_rn(v - __half2float(hi));
            size_t idx = (size_t)p * 1024 + (size_t)(k0 + tx - DIM);
            g_Whh[idx] = hi; g_Whl[idx] = lo;
        }
    }
}

// Pack bias gate-interleaved; zero initial h (buffer 0) and c; reset barrier.
__global__ void pack_bias_zero(const float* __restrict__ bf, const float* __restrict__ bi,
                               const float* __restrict__ bo, const float* __restrict__ bg) {
    int i = blockIdx.x * blockDim.x + threadIdx.x;   // 65536 threads
    if (i == 0) { g_bar_count = 0; g_bar_phase = 0; }
    if (i < 4096) {
        int gs = i & 3, j = i >> 2;
        const float* b = (gs == 0) ? bf : (gs == 1) ? bi : (gs == 2) ? bo : bg;
        g_bias[i] = b[j];
    }
    if (i < 65536) {
        g_c[i]     = 0.0f;
        g_hh[0][i] = __float2half_rn(0.0f);
    }
}

// Split x into bf16 hi/lo.
__global__ void split_x(const float* __restrict__ x) {
    size_t stride = (size_t)gridDim.x * blockDim.x;
    for (size_t i = (size_t)blockIdx.x * blockDim.x + threadIdx.x; i < 33554432u; i += stride) {
        float v = x[i];
        __nv_bfloat16 hi = __float2bfloat16_rn(v);
        g_xh[i] = hi;
        g_xl[i] = __float2bfloat16_rn(v - __bfloat162float(hi));
    }
}

// ---------------------------------------------------------------------------
// GEMM1: gates_x[M1, NPACK] = x[M1, DIM] @ Wx_packed[DIM, NPACK]
// 3xbf16 error-compensated. CTA tile 128x128, BK=32, 256 thr / 8 warps,
// 2-stage cp.async pipeline.  [R7-proven: 2.09 ms, tensor 65%]
// ---------------------------------------------------------------------------
typedef __nv_bfloat16 GTile[128][40];     // 10240 B
#define GEMM_SMEM 81920                   // 8 tiles (4 arrays x 2 stages)

__global__ __launch_bounds__(256) void gemm_x() {
    extern __shared__ __align__(16) unsigned char gsm[];
    GTile* Ash = (GTile*)(gsm);               // [2]
    GTile* Asl = (GTile*)(gsm + 20480);       // [2]
    GTile* Bsh = (GTile*)(gsm + 40960);       // [2]
    GTile* Bsl = (GTile*)(gsm + 61440);       // [2]

    const int bm = blockIdx.x >> 5;          // 0..255
    const int bn = blockIdx.x & 31;          // 0..31
    const size_t gm0 = (size_t)bm * 128;
    const size_t gn0 = (size_t)bn * 128;

    const int lane = threadIdx.x & 31, wid = threadIdx.x >> 5;
    const int wm = wid >> 2, wn = wid & 3;
    const int gid = lane >> 2, tig = lane & 3;

    float C[4][4][4];
    #pragma unroll
    for (int a = 0; a < 4; ++a)
        #pragma unroll
        for (int b = 0; b < 4; ++b)
            #pragma unroll
            for (int c = 0; c < 4; ++c) C[a][b][c] = 0.0f;

    auto load_slab = [&](int st, int it) {
        const int k0 = it * 32;
        #pragma unroll
        for (int s = threadIdx.x; s < 512; s += 256) {
            int r = s >> 2, q = (s & 3) * 8;
            cp_async16(&Ash[st][r][q], g_xh  + (gm0 + r) * 1024 + k0 + q);
            cp_async16(&Asl[st][r][q], g_xl  + (gm0 + r) * 1024 + k0 + q);
            cp_async16(&Bsh[st][r][q], g_Wxh + (gn0 + r) * 1024 + k0 + q);
            cp_async16(&Bsl[st][r][q], g_Wxl + (gn0 + r) * 1024 + k0 + q);
        }
        cp_commit();
    };

    load_slab(0, 0);

    for (int it = 0; it < 32; ++it) {
        const int b = it & 1;
        if (it < 31) { load_slab(b ^ 1, it + 1); cp_wait1(); }
        else         { cp_wait0(); }
        __syncthreads();

        #pragma unroll
        for (int kk = 0; kk < 32; kk += 16) {
            const int cb = kk + 2 * tig;
            uint32_t ah[4][4], al[4][4], bh[4][2], bl[4][2];
            #pragma unroll
            for (int mt = 0; mt < 4; ++mt) {
                int row = wm * 64 + mt * 16 + gid;
                ah[mt][0] = *(const uint32_t*)&Ash[b][row    ][cb    ];
                ah[mt][1] = *(const uint32_t*)&Ash[b][row + 8][cb    ];
                ah[mt][2] = *(const uint32_t*)&Ash[b][row    ][cb + 8];
                ah[mt][3] = *(const uint32_t*)&Ash[b][row + 8][cb + 8];
                al[mt][0] = *(const uint32_t*)&Asl[b][row    ][cb    ];
                al[mt][1] = *(const uint32_t*)&Asl[b][row + 8][cb    ];
                al[mt][2] = *(const uint32_t*)&Asl[b][row    ][cb + 8];
                al[mt][3] = *(const uint32_t*)&Asl[b][row + 8][cb + 8];
            }
            #pragma unroll
            for (int nt = 0; nt < 4; ++nt) {
                int nr = wn * 32 + nt * 8 + gid;
                bh[nt][0] = *(const uint32_t*)&Bsh[b][nr][cb    ];
                bh[nt][1] = *(const uint32_t*)&Bsh[b][nr][cb + 8];
                bl[nt][0] = *(const uint32_t*)&Bsl[b][nr][cb    ];
                bl[nt][1] = *(const uint32_t*)&Bsl[b][nr][cb + 8];
            }
            #pragma unroll
            for (int mt = 0; mt < 4; ++mt)
                #pragma unroll
                for (int nt = 0; nt < 4; ++nt) {
                    mma_bf16(C[mt][nt], ah[mt], bh[nt]);
                    mma_bf16(C[mt][nt], ah[mt], bl[nt]);
                    mma_bf16(C[mt][nt], al[mt], bh[nt]);
                }
        }
        __syncthreads();
    }

    #pragma unroll
    for (int mt = 0; mt < 4; ++mt)
        #pragma unroll
        for (int nt = 0; nt < 4; ++nt) {
            size_t row = gm0 + wm * 64 + mt * 16 + gid;
            size_t col = gn0 + wn * 32 + nt * 8 + 2 * tig;
            *(float2*)&g_gx[row * 4096 + col]       = make_float2(C[mt][nt][0], C[mt][nt][1]);
            *(float2*)&g_gx[(row + 8) * 4096 + col] = make_float2(C[mt][nt][2], C[mt][nt][3]);
        }
}

// ---------------------------------------------------------------------------
// Persistent recurrent kernel — R7 structure; fp16 h (single array) and
// fp16 W hi/lo (2-term product).  Central grid barrier (R7-proven).
// ---------------------------------------------------------------------------
struct SmemLayout {
    __half Wh[32][1032];     // 66,048 B  padded: conflict-free frags
    __half Wl[32][1032];     // 66,048
    __half Ah[2][64][136];   // 34,816   K-chunk 128, double buffered
};
#define SMEM_BYTES sizeof(SmemLayout)   // 166,912 B -> 1 CTA/SM

__device__ __forceinline__ void grid_bar(unsigned target) {
    __syncthreads();
    if (threadIdx.x == 0) {
        __threadfence();
        unsigned prev = atomicAdd(&g_bar_count, 1);
        if (prev == NCTA - 1) {
            g_bar_count = 0;
            __threadfence();
            atomicAdd(&g_bar_phase, 1);
        } else {
            unsigned p;
            do {
                asm volatile("ld.acquire.gpu.global.u32 %0, [%1];"
                             : "=r"(p) : "l"(&g_bar_phase));
            } while (p < target);
        }
    }
    __syncthreads();
}

__device__ __forceinline__ void lstm_update(int t, int r, int j,
                                            float pf, float pi, float po, float pg,
                                            int wb, float* __restrict__ out) {
    float f  = 1.0f / (1.0f + __expf(-pf));
    float ii = 1.0f / (1.0f + __expf(-pi));
    float o  = 1.0f / (1.0f + __expf(-po));
    float gg = tanhf(pg);
    int idx  = r * 1024 + j;
    float cn = f * g_c[idx] + ii * gg;
    g_c[idx] = cn;
    float h  = o * tanhf(cn);
    out[(size_t)t * 65536 + idx] = h;
    g_hh[wb][idx] = __float2half_rn(h);
}

__global__ __launch_bounds__(256, 1) void lstm_persist(float* __restrict__ out) {
    extern __shared__ __align__(16) unsigned char smem_raw[];
    SmemLayout& S = *reinterpret_cast<SmemLayout*>(smem_raw);

    const int tid  = threadIdx.x;
    const int lane = tid & 31, wid = tid >> 5;
    const int mt = wid & 3, nh = wid >> 2;       // warp tile: rows 16*mt, cols 16*nh
    const int g8  = lane >> 2, tig = lane & 3;
    const int P0  = blockIdx.x * 32;
    const int row = mt * 16 + g8;

    // One-time weight slice load: 32 rows x 1024 k, hi+lo (128 KB) into smem.
    for (int s = tid; s < 4096; s += 256) {
        int r = s >> 7, q = (s & 127) * 8;
        *(uint4*)&S.Wh[r][q] = *(const uint4*)(g_Whh + (size_t)(P0 + r) * 1024 + q);
        *(uint4*)&S.Wl[r][q] = *(const uint4*)(g_Whl + (size_t)(P0 + r) * 1024 + q);
    }
    __syncthreads();

    // Loop-invariant: packed columns + bias for this thread's epilogue.
    int pcol[2];  float vb[2][2];
    #pragma unroll
    for (int nb = 0; nb < 2; ++nb) {
        pcol[nb] = P0 + nh * 16 + nb * 8 + 2 * tig;
        vb[nb][0] = g_bias[pcol[nb]];
        vb[nb][1] = g_bias[pcol[nb] + 1];
    }

    for (int t = 0; t < T_SEQ; ++t) {
        const int rb = t & 1, wb = rb ^ 1;
        const __half* __restrict__ hh = g_hh[rb];
        const float* __restrict__ gx = g_gx + (size_t)t * BATCH * 4096;

        // Prefetch this thread's gates_x operands (streaming; hidden by compute).
        float2 vg[2][2];
        #pragma unroll
        for (int nb = 0; nb < 2; ++nb) {
            int p = pcol[nb];
            vg[nb][0] = __ldcs((const float2*)&gx[(size_t)row * 4096 + p]);
            vg[nb][1] = __ldcs((const float2*)&gx[(size_t)(row + 8) * 4096 + p]);
        }

        float C[2][4] = {};

        // Preload chunk 0 of h (fp16, one array -> 1024 cp.async).
        for (int s = tid; s < 1024; s += 256) {
            int r = s >> 4, q = (s & 15) * 8;
            cp_async16(&S.Ah[0][r][q], hh + r * 1024 + q);
        }
        cp_commit();

        for (int it = 0; it < 8; ++it) {
            if (it < 7) {
                const int k0 = (it + 1) * 128, b = (it + 1) & 1;
                for (int s = tid; s < 1024; s += 256) {
                    int r = s >> 4, q = (s & 15) * 8;
                    cp_async16(&S.Ah[b][r][q], hh + r * 1024 + k0 + q);
                }
                cp_commit();
                cp_wait1();
            } else {
                cp_wait0();
            }
            __syncthreads();
            const int b = it & 1;
            #pragma unroll
            for (int kk = 0; kk < 128; kk += 16) {
                const int ca = kk + 2 * tig;          // k within chunk (A)
                const int cw = it * 128 + ca;         // global k (W, fully resident)
                uint32_t ah[4];
                ah[0] = *(const uint32_t*)&S.Ah[b][row    ][ca    ];
                ah[1] = *(const uint32_t*)&S.Ah[b][row + 8][ca    ];
                ah[2] = *(const uint32_t*)&S.Ah[b][row    ][ca + 8];
                ah[3] = *(const uint32_t*)&S.Ah[b][row + 8][ca + 8];
                #pragma unroll
                for (int nb = 0; nb < 2; ++nb) {
                    const int nr = nh * 16 + nb * 8 + g8;
                    uint32_t bh[2], bl[2];
                    bh[0] = *(const uint32_t*)&S.Wh[nr][cw    ];
                    bh[1] = *(const uint32_t*)&S.Wh[nr][cw + 8];
                    bl[0] = *(const uint32_t*)&S.Wl[nr][cw    ];
                    bl[1] = *(const uint32_t*)&S.Wl[nr][cw + 8];
                    mma_f16(C[nb], ah, bh);
                    mma_f16(C[nb], ah, bl);
                }
            }
            __syncthreads();
        }

        // Epilogue: add x-part + bias, pair-exchange (f,i)<->(o,g), update cell.
        #pragma unroll
        for (int nb = 0; nb < 2; ++nb) {
            float v0 = C[nb][0] + vg[nb][0].x + vb[nb][0];
            float v1 = C[nb][1] + vg[nb][0].y + vb[nb][1];
            float v2 = C[nb][2] + vg[nb][1].x + vb[nb][0];
            float v3 = C[nb][3] + vg[nb][1].y + vb[nb][1];
            float q0 = __shfl_xor_sync(0xffffffffu, v0, 1);
            float q1 = __shfl_xor_sync(0xffffffffu, v1, 1);
            float q2 = __shfl_xor_sync(0xffffffffu, v2, 1);
            float q3 = __shfl_xor_sync(0xffffffffu, v3, 1);
            if ((lane & 1) == 0) {               // holds (f,i); partner held (o,g)
                int j = pcol[nb] >> 2;
                lstm_update(t, row,     j, v0, v1, q0, q1, wb, out);
                lstm_update(t, row + 8, j, v2, v3, q2, q3, wb, out);
            }
        }

        if (t < T_SEQ - 1) grid_bar((unsigned)(t + 1));
    }
}

// ---------------------------------------------------------------------------
// Launch: default stream, fully capturable; one persistent recurrent kernel.
// ---------------------------------------------------------------------------
extern "C" void kernel_launch(void* const* d_in, const int* in_sizes, int n_in,
                              void* d_out, int out_size) {
    const float* x  = (const float*)d_in[0];
    const float* Wf = (const float*)d_in[1];
    const float* bf = (const float*)d_in[2];
    const float* Wi = (const float*)d_in[3];
    const float* bi = (const float*)d_in[4];
    const float* Wo = (const float*)d_in[5];
    const float* bo = (const float*)d_in[6];
    const float* Wg = (const float*)d_in[7];
    const float* bg = (const float*)d_in[8];
    float* out = (float*)d_out;

    cudaFuncSetAttribute(gemm_x, cudaFuncAttributeMaxDynamicSharedMemorySize,
                         GEMM_SMEM);
    cudaFuncSetAttribute(lstm_persist, cudaFuncAttributeMaxDynamicSharedMemorySize,
                         (int)SMEM_BYTES);

    prep_weights<<<dim3(64, 32, 4), 256>>>(Wf, Wi, Wo, Wg);
    pack_bias_zero<<<256, 256>>>(bf, bi, bo, bg);
    split_x<<<8192, 256>>>(x);
    gemm_x<<<8192, 256, GEMM_SMEM>>>();
    lstm_persist<<<NCTA, 256, SMEM_BYTES>>>(out);
}

// round 16
// speedup vs baseline: 1.4840x; 1.0627x over previous
#include <cuda_runtime.h>
#include <cuda_bf16.h>
#include <cuda_fp16.h>
#include <stdint.h>

// Problem constants
#define T_SEQ 512
#define BATCH 64
#define DIM   1024
#define LAT   1024
#define NPACK 4096            // 4*LAT, gate-interleaved packed columns: p = 4*j + g
#define M1    32768           // T_SEQ*BATCH
#define NCTA  128             // persistent grid (<=148 SMs, 1 CTA/SM)

// ---------------------------------------------------------------------------
// Device scratch (static __device__ arrays; no allocations anywhere)
// ---------------------------------------------------------------------------
__device__ float          g_gx[134217728];          // [M1][NPACK] fp32 x-part gates (512 MB)
__device__ __nv_bfloat16  g_Wxh[4194304], g_Wxl[4194304];  // Wx packed [NPACK][DIM] bf16 hi/lo
__device__ __half         g_Whh[4194304];                  // Wh packed [NPACK][LAT] fp16
__device__ __nv_bfloat16  g_xh[33554432], g_xl[33554432];  // x split   [M1][DIM]    bf16 hi/lo
__device__ __half         g_hh[2][65536];                  // h state double-buffered, fp16
__device__ float          g_c[65536];                       // c state fp32
__device__ float          g_bias[4096];                     // packed bias
__device__ unsigned       g_bar_count;                      // central grid barrier (proven)
__device__ unsigned       g_bar_phase;

// ---------------------------------------------------------------------------
// mma.sync m16n8k16 helpers (fp32 accumulate)
// ---------------------------------------------------------------------------
__device__ __forceinline__ void mma_bf16(float c[4], const uint32_t a[4], const uint32_t b[2]) {
    asm volatile(
        "mma.sync.aligned.m16n8k16.row.col.f32.bf16.bf16.f32 "
        "{%0,%1,%2,%3}, {%4,%5,%6,%7}, {%8,%9}, {%0,%1,%2,%3};\n"
        : "+f"(c[0]), "+f"(c[1]), "+f"(c[2]), "+f"(c[3])
        : "r"(a[0]), "r"(a[1]), "r"(a[2]), "r"(a[3]), "r"(b[0]), "r"(b[1]));
}
__device__ __forceinline__ void mma_f16(float c[4], const uint32_t a[4], const uint32_t b[2]) {
    asm volatile(
        "mma.sync.aligned.m16n8k16.row.col.f32.f16.f16.f32 "
        "{%0,%1,%2,%3}, {%4,%5,%6,%7}, {%8,%9}, {%0,%1,%2,%3};\n"
        : "+f"(c[0]), "+f"(c[1]), "+f"(c[2]), "+f"(c[3])
        : "r"(a[0]), "r"(a[1]), "r"(a[2]), "r"(a[3]), "r"(b[0]), "r"(b[1]));
}

// cp.async helpers (16B, L2-only path: .cg)
__device__ __forceinline__ void cp_async16(void* sptr, const void* gptr) {
    uint32_t s = (uint32_t)__cvta_generic_to_shared(sptr);
    asm volatile("cp.async.cg.shared.global [%0], [%1], 16;\n" :: "r"(s), "l"(gptr));
}
__device__ __forceinline__ void cp_commit() { asm volatile("cp.async.commit_group;\n"); }
__device__ __forceinline__ void cp_wait1()  { asm volatile("cp.async.wait_group 1;\n"); }
__device__ __forceinline__ void cp_wait0()  { asm volatile("cp.async.wait_group 0;\n"); }

// ---------------------------------------------------------------------------
// Prep: transpose + gate-interleave + split of the 4 gate weights.
// x-rows (k<DIM)  -> bf16 hi/lo (exact 3-term path in gemm_x)
// h-rows (k>=DIM) -> single fp16 (1-term path in lstm_persist)
// ---------------------------------------------------------------------------
__global__ void prep_weights(const float* __restrict__ Wf, const float* __restrict__ Wi,
                             const float* __restrict__ Wo, const float* __restrict__ Wg) {
    __shared__ float tile[32][33];
    const int g  = blockIdx.z;
    const float* W = (g == 0) ? Wf : (g == 1) ? Wi : (g == 2) ? Wo : Wg;
    const int k0 = blockIdx.x * 32;     // 0..2047 (k index in D+L)
    const int j0 = blockIdx.y * 32;     // 0..1023
    const int tx = threadIdx.x & 31;
    const int ty = threadIdx.x >> 5;    // 0..7

    for (int r = ty; r < 32; r += 8)
        tile[r][tx] = W[(size_t)(k0 + r) * LAT + (j0 + tx)];
    __syncthreads();

    const bool isx = (k0 < DIM);
    for (int lj = ty; lj < 32; lj += 8) {
        float v = tile[tx][lj];                                   // (k0+tx, j0+lj)
        int p = 4 * (j0 + lj) + g;
        if (isx) {
            __nv_bfloat16 hi = __float2bfloat16_rn(v);
            __nv_bfloat16 lo = __float2bfloat16_rn(v - __bfloat162float(hi));
            size_t idx = (size_t)p * 1024 + (size_t)(k0 + tx);
            g_Wxh[idx] = hi; g_Wxl[idx] = lo;
        } else {
            size_t idx = (size_t)p * 1024 + (size_t)(k0 + tx - DIM);
            g_Whh[idx] = __float2half_rn(v);
        }
    }
}

// Pack bias gate-interleaved; zero initial h (buffer 0) and c; reset barrier.
__global__ void pack_bias_zero(const float* __restrict__ bf, const float* __restrict__ bi,
                               const float* __restrict__ bo, const float* __restrict__ bg) {
    int i = blockIdx.x * blockDim.x + threadIdx.x;   // 65536 threads
    if (i == 0) { g_bar_count = 0; g_bar_phase = 0; }
    if (i < 4096) {
        int gs = i & 3, j = i >> 2;
        const float* b = (gs == 0) ? bf : (gs == 1) ? bi : (gs == 2) ? bo : bg;
        g_bias[i] = b[j];
    }
    if (i < 65536) {
        g_c[i]     = 0.0f;
        g_hh[0][i] = __float2half_rn(0.0f);
    }
}

// Split x into bf16 hi/lo.
__global__ void split_x(const float* __restrict__ x) {
    size_t stride = (size_t)gridDim.x * blockDim.x;
    for (size_t i = (size_t)blockIdx.x * blockDim.x + threadIdx.x; i < 33554432u; i += stride) {
        float v = x[i];
        __nv_bfloat16 hi = __float2bfloat16_rn(v);
        g_xh[i] = hi;
        g_xl[i] = __float2bfloat16_rn(v - __bfloat162float(hi));
    }
}

// ---------------------------------------------------------------------------
// GEMM1: gates_x[M1, NPACK] = x[M1, DIM] @ Wx_packed[DIM, NPACK]
// 3xbf16 error-compensated. CTA tile 128x128, BK=32, 256 thr / 8 warps,
// 2-stage cp.async pipeline.  [R7-proven: 2.09 ms, tensor 65%]
// ---------------------------------------------------------------------------
typedef __nv_bfloat16 GTile[128][40];     // 10240 B
#define GEMM_SMEM 81920                   // 8 tiles (4 arrays x 2 stages)

__global__ __launch_bounds__(256) void gemm_x() {
    extern __shared__ __align__(16) unsigned char gsm[];
    GTile* Ash = (GTile*)(gsm);               // [2]
    GTile* Asl = (GTile*)(gsm + 20480);       // [2]
    GTile* Bsh = (GTile*)(gsm + 40960);       // [2]
    GTile* Bsl = (GTile*)(gsm + 61440);       // [2]

    const int bm = blockIdx.x >> 5;          // 0..255
    const int bn = blockIdx.x & 31;          // 0..31
    const size_t gm0 = (size_t)bm * 128;
    const size_t gn0 = (size_t)bn * 128;

    const int lane = threadIdx.x & 31, wid = threadIdx.x >> 5;
    const int wm = wid >> 2, wn = wid & 3;
    const int gid = lane >> 2, tig = lane & 3;

    float C[4][4][4];
    #pragma unroll
    for (int a = 0; a < 4; ++a)
        #pragma unroll
        for (int b = 0; b < 4; ++b)
            #pragma unroll
            for (int c = 0; c < 4; ++c) C[a][b][c] = 0.0f;

    auto load_slab = [&](int st, int it) {
        const int k0 = it * 32;
        #pragma unroll
        for (int s = threadIdx.x; s < 512; s += 256) {
            int r = s >> 2, q = (s & 3) * 8;
            cp_async16(&Ash[st][r][q], g_xh  + (gm0 + r) * 1024 + k0 + q);
            cp_async16(&Asl[st][r][q], g_xl  + (gm0 + r) * 1024 + k0 + q);
            cp_async16(&Bsh[st][r][q], g_Wxh + (gn0 + r) * 1024 + k0 + q);
            cp_async16(&Bsl[st][r][q], g_Wxl + (gn0 + r) * 1024 + k0 + q);
        }
        cp_commit();
    };

    load_slab(0, 0);

    for (int it = 0; it < 32; ++it) {
        const int b = it & 1;
        if (it < 31) { load_slab(b ^ 1, it + 1); cp_wait1(); }
        else         { cp_wait0(); }
        __syncthreads();

        #pragma unroll
        for (int kk = 0; kk < 32; kk += 16) {
            const int cb = kk + 2 * tig;
            uint32_t ah[4][4], al[4][4], bh[4][2], bl[4][2];
            #pragma unroll
            for (int mt = 0; mt < 4; ++mt) {
                int row = wm * 64 + mt * 16 + gid;
                ah[mt][0] = *(const uint32_t*)&Ash[b][row    ][cb    ];
                ah[mt][1] = *(const uint32_t*)&Ash[b][row + 8][cb    ];
                ah[mt][2] = *(const uint32_t*)&Ash[b][row    ][cb + 8];
                ah[mt][3] = *(const uint32_t*)&Ash[b][row + 8][cb + 8];
                al[mt][0] = *(const uint32_t*)&Asl[b][row    ][cb    ];
                al[mt][1] = *(const uint32_t*)&Asl[b][row + 8][cb    ];
                al[mt][2] = *(const uint32_t*)&Asl[b][row    ][cb + 8];
                al[mt][3] = *(const uint32_t*)&Asl[b][row + 8][cb + 8];
            }
            #pragma unroll
            for (int nt = 0; nt < 4; ++nt) {
                int nr = wn * 32 + nt * 8 + gid;
                bh[nt][0] = *(const uint32_t*)&Bsh[b][nr][cb    ];
                bh[nt][1] = *(const uint32_t*)&Bsh[b][nr][cb + 8];
                bl[nt][0] = *(const uint32_t*)&Bsl[b][nr][cb    ];
                bl[nt][1] = *(const uint32_t*)&Bsl[b][nr][cb + 8];
            }
            #pragma unroll
            for (int mt = 0; mt < 4; ++mt)
                #pragma unroll
                for (int nt = 0; nt < 4; ++nt) {
                    mma_bf16(C[mt][nt], ah[mt], bh[nt]);
                    mma_bf16(C[mt][nt], ah[mt], bl[nt]);
                    mma_bf16(C[mt][nt], al[mt], bh[nt]);
                }
        }
        __syncthreads();
    }

    #pragma unroll
    for (int mt = 0; mt < 4; ++mt)
        #pragma unroll
        for (int nt = 0; nt < 4; ++nt) {
            size_t row = gm0 + wm * 64 + mt * 16 + gid;
            size_t col = gn0 + wn * 32 + nt * 8 + 2 * tig;
            *(float2*)&g_gx[row * 4096 + col]       = make_float2(C[mt][nt][0], C[mt][nt][1]);
            *(float2*)&g_gx[(row + 8) * 4096 + col] = make_float2(C[mt][nt][2], C[mt][nt][3]);
        }
}

// ---------------------------------------------------------------------------
// Persistent recurrent kernel — R7 structure; fp16 h x fp16 W, SINGLE term.
// Central grid barrier (proven).  Smem ~101 KB.
// ---------------------------------------------------------------------------
struct SmemLayout {
    __half Wh[32][1032];     // 66,048 B  padded: conflict-free frags
    __half Ah[2][64][136];   // 34,816    K-chunk 128, double buffered
};
#define SMEM_BYTES sizeof(SmemLayout)   // 100,864 B

__device__ __forceinline__ void grid_bar(unsigned target) {
    __syncthreads();
    if (threadIdx.x == 0) {
        __threadfence();
        unsigned prev = atomicAdd(&g_bar_count, 1);
        if (prev == NCTA - 1) {
            g_bar_count = 0;
            __threadfence();
            atomicAdd(&g_bar_phase, 1);
        } else {
            unsigned p;
            do {
                asm volatile("ld.acquire.gpu.global.u32 %0, [%1];"
                             : "=r"(p) : "l"(&g_bar_phase));
            } while (p < target);
        }
    }
    __syncthreads();
}

__device__ __forceinline__ void lstm_update(int t, int r, int j,
                                            float pf, float pi, float po, float pg,
                                            int wb, float* __restrict__ out) {
    float f  = 1.0f / (1.0f + __expf(-pf));
    float ii = 1.0f / (1.0f + __expf(-pi));
    float o  = 1.0f / (1.0f + __expf(-po));
    float gg = tanhf(pg);
    int idx  = r * 1024 + j;
    float cn = f * g_c[idx] + ii * gg;
    g_c[idx] = cn;
    float h  = o * tanhf(cn);
    out[(size_t)t * 65536 + idx] = h;
    g_hh[wb][idx] = __float2half_rn(h);
}

__global__ __launch_bounds__(256, 1) void lstm_persist(float* __restrict__ out) {
    extern __shared__ __align__(16) unsigned char smem_raw[];
    SmemLayout& S = *reinterpret_cast<SmemLayout*>(smem_raw);

    const int tid  = threadIdx.x;
    const int lane = tid & 31, wid = tid >> 5;
    const int mt = wid & 3, nh = wid >> 2;       // warp tile: rows 16*mt, cols 16*nh
    const int g8  = lane >> 2, tig = lane & 3;
    const int P0  = blockIdx.x * 32;
    const int row = mt * 16 + g8;

    // One-time weight slice load: 32 rows x 1024 k fp16 (64 KB) into smem.
    for (int s = tid; s < 4096; s += 256) {
        int r = s >> 7, q = (s & 127) * 8;
        *(uint4*)&S.Wh[r][q] = *(const uint4*)(g_Whh + (size_t)(P0 + r) * 1024 + q);
    }
    __syncthreads();

    // Loop-invariant: packed columns + bias for this thread's epilogue.
    int pcol[2];  float vb[2][2];
    #pragma unroll
    for (int nb = 0; nb < 2; ++nb) {
        pcol[nb] = P0 + nh * 16 + nb * 8 + 2 * tig;
        vb[nb][0] = g_bias[pcol[nb]];
        vb[nb][1] = g_bias[pcol[nb] + 1];
    }

    for (int t = 0; t < T_SEQ; ++t) {
        const int rb = t & 1, wb = rb ^ 1;
        const __half* __restrict__ hh = g_hh[rb];
        const float* __restrict__ gx = g_gx + (size_t)t * BATCH * 4096;

        // Prefetch this thread's gates_x operands (streaming; hidden by compute).
        float2 vg[2][2];
        #pragma unroll
        for (int nb = 0; nb < 2; ++nb) {
            int p = pcol[nb];
            vg[nb][0] = __ldcs((const float2*)&gx[(size_t)row * 4096 + p]);
            vg[nb][1] = __ldcs((const float2*)&gx[(size_t)(row + 8) * 4096 + p]);
        }

        float C[2][4] = {};

        // Preload chunk 0 of h (fp16 -> 1024 cp.async).
        for (int s = tid; s < 1024; s += 256) {
            int r = s >> 4, q = (s & 15) * 8;
            cp_async16(&S.Ah[0][r][q], hh + r * 1024 + q);
        }
        cp_commit();

        for (int it = 0; it < 8; ++it) {
            if (it < 7) {
                const int k0 = (it + 1) * 128, b = (it + 1) & 1;
                for (int s = tid; s < 1024; s += 256) {
                    int r = s >> 4, q = (s & 15) * 8;
                    cp_async16(&S.Ah[b][r][q], hh + r * 1024 + k0 + q);
                }
                cp_commit();
                cp_wait1();
            } else {
                cp_wait0();
            }
            __syncthreads();
            const int b = it & 1;
            #pragma unroll
            for (int kk = 0; kk < 128; kk += 16) {
                const int ca = kk + 2 * tig;          // k within chunk (A)
                const int cw = it * 128 + ca;         // global k (W, fully resident)
                uint32_t ah[4];
                ah[0] = *(const uint32_t*)&S.Ah[b][row    ][ca    ];
                ah[1] = *(const uint32_t*)&S.Ah[b][row + 8][ca    ];
                ah[2] = *(const uint32_t*)&S.Ah[b][row    ][ca + 8];
                ah[3] = *(const uint32_t*)&S.Ah[b][row + 8][ca + 8];
                #pragma unroll
                for (int nb = 0; nb < 2; ++nb) {
                    const int nr = nh * 16 + nb * 8 + g8;
                    uint32_t bh[2];
                    bh[0] = *(const uint32_t*)&S.Wh[nr][cw    ];
                    bh[1] = *(const uint32_t*)&S.Wh[nr][cw + 8];
                    mma_f16(C[nb], ah, bh);
                }
            }
            __syncthreads();
        }

        // Epilogue: add x-part + bias, pair-exchange (f,i)<->(o,g), update cell.
        #pragma unroll
        for (int nb = 0; nb < 2; ++nb) {
            float v0 = C[nb][0] + vg[nb][0].x + vb[nb][0];
            float v1 = C[nb][1] + vg[nb][0].y + vb[nb][1];
            float v2 = C[nb][2] + vg[nb][1].x + vb[nb][0];
            float v3 = C[nb][3] + vg[nb][1].y + vb[nb][1];
            float q0 = __shfl_xor_sync(0xffffffffu, v0, 1);
            float q1 = __shfl_xor_sync(0xffffffffu, v1, 1);
            float q2 = __shfl_xor_sync(0xffffffffu, v2, 1);
            float q3 = __shfl_xor_sync(0xffffffffu, v3, 1);
            if ((lane & 1) == 0) {               // holds (f,i); partner held (o,g)
                int j = pcol[nb] >> 2;
                lstm_update(t, row,     j, v0, v1, q0, q1, wb, out);
                lstm_update(t, row + 8, j, v2, v3, q2, q3, wb, out);
            }
        }

        if (t < T_SEQ - 1) grid_bar((unsigned)(t + 1));
    }
}

// ---------------------------------------------------------------------------
// Launch: default stream, fully capturable; one persistent recurrent kernel.
// ---------------------------------------------------------------------------
extern "C" void kernel_launch(void* const* d_in, const int* in_sizes, int n_in,
                              void* d_out, int out_size) {
    const float* x  = (const float*)d_in[0];
    const float* Wf = (const float*)d_in[1];
    const float* bf = (const float*)d_in[2];
    const float* Wi = (const float*)d_in[3];
    const float* bi = (const float*)d_in[4];
    const float* Wo = (const float*)d_in[5];
    const float* bo = (const float*)d_in[6];
    const float* Wg = (const float*)d_in[7];
    const float* bg = (const float*)d_in[8];
    float* out = (float*)d_out;

    cudaFuncSetAttribute(gemm_x, cudaFuncAttributeMaxDynamicSharedMemorySize,
                         GEMM_SMEM);
    cudaFuncSetAttribute(lstm_persist, cudaFuncAttributeMaxDynamicSharedMemorySize,
                         (int)SMEM_BYTES);

    prep_weights<<<dim3(64, 32, 4), 256>>>(Wf, Wi, Wo, Wg);
    pack_bias_zero<<<256, 256>>>(bf, bi, bo, bg);
    split_x<<<8192, 256>>>(x);
    gemm_x<<<8192, 256, GEMM_SMEM>>>();
    lstm_persist<<<NCTA, 256, SMEM_BYTES>>>(out);
}